// round 16
// baseline (speedup 1.0000x reference)
#include <cuda_runtime.h>
#include <cuda_fp16.h>
#include <cstdint>
#include <math.h>

// ---------------- problem constants ----------------
#define Bsz   4096
#define Hn    512
#define H3    1536
#define Ln    3
#define Tn    16
#define Cn    512
#define NSTEP 17
#define KDIM  512
#define NCH   8            // K chunks of 64 fp16 (128B rows)

static const size_t BH  = (size_t)Bsz * Hn;
static const size_t BH3 = (size_t)Bsz * H3;

// ---------------- persistent device scratch ----------------
__device__ __align__(128) __half g_u0[(size_t)NSTEP * Bsz * Hn];
__device__ __align__(128) __half g_u1[(size_t)NSTEP * Bsz * Hn];
__device__ __align__(128) __half g_u2[(size_t)NSTEP * Bsz * Hn];
__device__ __align__(128) __half g_x0h[(size_t)Bsz * Hn];
__device__ __align__(128) __half g_x0l[(size_t)Bsz * Hn];
__device__ __align__(128) __half g_pq_hi[(size_t)Ln * Bsz * Hn];
__device__ __align__(128) __half g_GIh[(size_t)Bsz * H3];          // slot0 only
__device__ __align__(128) __half g_wih[(size_t)Ln * H3 * Hn];
__device__ __align__(128) __half g_whh[(size_t)Ln * H3 * Hn];
__device__ __align__(128) __half g_wo[(size_t)Cn * Hn];
__device__ __align__(128) __half g_wt[(size_t)Hn * Hn];
__device__ __align__(128) __half g_embh[(size_t)Cn * Hn];
__device__ __align__(128) __half g_embl[(size_t)Cn * Hn];
__device__ __align__(128) float  g_P[(size_t)Cn * Hn];
__device__ __align__(128) __half g_Pqh[(size_t)Cn * Hn];
__device__ __align__(128) __half g_Pql[(size_t)Cn * Hn];
__device__ __align__(128) __half g_Gtabh[(size_t)Cn * H3];

// ---------------- PTX helpers ----------------
__device__ __forceinline__ uint32_t smem_u32(const void* p) {
    uint32_t a;
    asm("{ .reg .u64 t; cvta.to.shared.u64 t, %1; cvt.u32.u64 %0, t; }" : "=r"(a) : "l"(p));
    return a;
}
__device__ __forceinline__ void cpasync16(uint32_t s, const void* g) {
    asm volatile("cp.async.cg.shared.global [%0], [%1], 16;" :: "r"(s), "l"(g));
}
__device__ __forceinline__ void cp_commit() {
    asm volatile("cp.async.commit_group;" ::: "memory");
}
template <int N> __device__ __forceinline__ void cp_wait() {
    asm volatile("cp.async.wait_group %0;" :: "n"(N) : "memory");
}
__device__ __forceinline__ void ldsm4(uint32_t& r0, uint32_t& r1, uint32_t& r2, uint32_t& r3,
                                      uint32_t addr) {
    asm volatile("ldmatrix.sync.aligned.m8n8.x4.shared.b16 {%0,%1,%2,%3}, [%4];"
                 : "=r"(r0), "=r"(r1), "=r"(r2), "=r"(r3) : "r"(addr));
}
__device__ __forceinline__ void hmma16816(float* d, const uint32_t* a, uint32_t b0, uint32_t b1) {
    asm volatile(
        "mma.sync.aligned.m16n8k16.row.col.f32.f16.f16.f32 "
        "{%0,%1,%2,%3}, {%4,%5,%6,%7}, {%8,%9}, {%0,%1,%2,%3};"
        : "+f"(d[0]), "+f"(d[1]), "+f"(d[2]), "+f"(d[3])
        : "r"(a[0]), "r"(a[1]), "r"(a[2]), "r"(a[3]), "r"(b0), "r"(b1));
}

#define GEMM_SMEM2 (2 * 49152)
#define GEMM_SMEM1 (2 * 32768)
#define STEP_SMEM  (3 * 28672)   // step kernels: 3-stage pipeline

__device__ __forceinline__ float sigf(float x) { return 1.f / (1.f + __expf(-x)); }
__device__ __forceinline__ void split1h(float x, __half& h, __half& l) {
    h = __float2half_rn(x);
    l = __float2half_rn(x - __half2float(h));
}

// ---------------------------------------------------------------------------
// fp16 GEMM, 128x128 tile. PLANES: A planes. OUTH: 1 => fp16 C.
// MODE 0: row-major C (ld = ldc_or_slot).
// MODE 3: logits chunk: C[b, slot, n] fp32, slot = ldc_or_slot.
// ---------------------------------------------------------------------------
template <int MODE, int PLANES, int OUTH>
__global__ void __launch_bounds__(256, 2)
gemm_h2(const __half* __restrict__ Ahi, const __half* __restrict__ Alo,
        const __half* __restrict__ Bh,
        const float* __restrict__ bias, void* __restrict__ Cv, int ldc_or_slot)
{
    constexpr int STAGE = (PLANES == 2) ? 49152 : 32768;
    constexpr int BOFF  = PLANES * 16384;
    extern __shared__ __align__(128) char smem[];
    const uint32_t sb = smem_u32(smem);
    const int tid  = threadIdx.x;
    const int wid  = tid >> 5, lane = tid & 31;
    const int wM   = wid >> 1;
    const int wN   = wid & 1;
    const int m0   = blockIdx.y << 7, n0 = blockIdx.x << 7;

    const char* gAh = (const char*)(Ahi + (size_t)m0 * KDIM);
    const char* gAl = (const char*)(Alo + (size_t)m0 * KDIM);
    const char* gB  = (const char*)(Bh  + (size_t)n0 * KDIM);

    int srow[4], soff[4]; uint32_t sso[4];
#pragma unroll
    for (int q = 0; q < 4; q++) {
        int id = tid * 4 + q;
        srow[q] = id >> 3;
        soff[q] = (id & 7) << 4;
        sso[q]  = (uint32_t)((srow[q] << 7) | (soff[q] ^ ((srow[q] & 7) << 4)));
    }

    const int lr16 = lane & 15;
    const int lhi  = (lane >> 4) << 4;
    uint32_t aBase[2], aXr[2];
#pragma unroll
    for (int mt = 0; mt < 2; mt++) {
        int r = wM * 32 + mt * 16 + lr16;
        aBase[mt] = (uint32_t)(r << 7);
        aXr[mt]   = ((r & 7) << 4);
    }
    uint32_t bBase[4], bXr[4];
#pragma unroll
    for (int nt = 0; nt < 4; nt++) {
        int r = wN * 64 + nt * 16 + lr16;
        bBase[nt] = (uint32_t)(r << 7);
        bXr[nt]   = ((r & 7) << 4);
    }

    float acc[2][8][4];
#pragma unroll
    for (int i = 0; i < 2; i++)
#pragma unroll
        for (int j = 0; j < 8; j++)
#pragma unroll
            for (int v = 0; v < 4; v++) acc[i][j][v] = 0.f;

    auto load_chunk = [&](int s, int c) {
        const uint32_t st = sb + s * STAGE;
        const int cb = c * 128;
#pragma unroll
        for (int q = 0; q < 4; q++) {
            int go = srow[q] * 1024 + cb + soff[q];
            cpasync16(st + sso[q], gAh + go);
            if (PLANES == 2) cpasync16(st + 16384 + sso[q], gAl + go);
            cpasync16(st + BOFF + sso[q], gB + go);
        }
        cp_commit();
    };

    load_chunk(0, 0);

    for (int c = 0; c < NCH; c++) {
        const int s = c & 1;
        if (c + 1 < NCH) { load_chunk(s ^ 1, c + 1); cp_wait<1>(); }
        else             { cp_wait<0>(); }
        __syncthreads();

        const uint32_t stA0 = sb + s * STAGE;
        const uint32_t stA1 = stA0 + 16384;
        const uint32_t stB0 = stA0 + BOFF;

#pragma unroll
        for (int k16 = 0; k16 < 4; k16++) {
            const uint32_t ko = (uint32_t)(k16 * 32 + lhi);
            uint32_t ah[2][4], al[2][4];
#pragma unroll
            for (int mt = 0; mt < 2; mt++) {
                ldsm4(ah[mt][0], ah[mt][1], ah[mt][2], ah[mt][3],
                      stA0 + aBase[mt] + (ko ^ aXr[mt]));
                if (PLANES == 2)
                    ldsm4(al[mt][0], al[mt][1], al[mt][2], al[mt][3],
                          stA1 + aBase[mt] + (ko ^ aXr[mt]));
            }
            uint32_t bh[4][4];
#pragma unroll
            for (int nt = 0; nt < 4; nt++)
                ldsm4(bh[nt][0], bh[nt][1], bh[nt][2], bh[nt][3],
                      stB0 + bBase[nt] + (ko ^ bXr[nt]));
#pragma unroll
            for (int mt = 0; mt < 2; mt++)
#pragma unroll
                for (int nt = 0; nt < 4; nt++) {
                    hmma16816(acc[mt][2 * nt + 0], ah[mt], bh[nt][0], bh[nt][2]);
                    hmma16816(acc[mt][2 * nt + 1], ah[mt], bh[nt][1], bh[nt][3]);
                    if (PLANES == 2) {
                        hmma16816(acc[mt][2 * nt + 0], al[mt], bh[nt][0], bh[nt][2]);
                        hmma16816(acc[mt][2 * nt + 1], al[mt], bh[nt][1], bh[nt][3]);
                    }
                }
        }
        __syncthreads();
    }

    const int lr = lane >> 2;
    const int lc = (lane & 3) << 1;
#pragma unroll
    for (int mt = 0; mt < 2; mt++) {
        const int mBase = m0 + wM * 32 + mt * 16 + lr;
#pragma unroll
        for (int nt = 0; nt < 8; nt++) {
            const int n = n0 + wN * 64 + nt * 8 + lc;
            const float b0 = bias[n], b1 = bias[n + 1];
            float2 v0 = make_float2(acc[mt][nt][0] + b0, acc[mt][nt][1] + b1);
            float2 v1 = make_float2(acc[mt][nt][2] + b0, acc[mt][nt][3] + b1);
            size_t o0, o1;
            if (MODE == 3) {
                o0 = (size_t)mBase * (Tn * Cn) + (size_t)ldc_or_slot * Cn + n;
                o1 = (size_t)(mBase + 8) * (Tn * Cn) + (size_t)ldc_or_slot * Cn + n;
            } else {
                o0 = (size_t)mBase * ldc_or_slot + n;
                o1 = (size_t)(mBase + 8) * ldc_or_slot + n;
            }
            if (OUTH) {
                __half* C = (__half*)Cv;
                *(__half2*)(C + o0) = __floats2half2_rn(v0.x, v0.y);
                *(__half2*)(C + o1) = __floats2half2_rn(v1.x, v1.y);
            } else {
                float* C = (float*)Cv;
                *(float2*)(C + o0) = v0;
                *(float2*)(C + o1) = v1;
            }
        }
    }
}

// ---------------------------------------------------------------------------
// Layer-0 GRU step, fp16 carried state. GH GEMM + gate math; h_prev for the
// z-blend is read from the fp16 A buffer itself. Optional fp32 state output.
// GIMODE: 0 = fp16 GI slice [B,3H]; 1 = fp32 bias row; 2 = fp16 token table.
// ---------------------------------------------------------------------------
template <int GIMODE>
__global__ void __launch_bounds__(256, 2)
gru_step(const __half* __restrict__ Ahi,
         const __half* __restrict__ W, const float* __restrict__ bhh,
         const void* __restrict__ GIt, const int* __restrict__ gt, int step,
         float* __restrict__ houtF, __half* __restrict__ hi)
{
    extern __shared__ __align__(128) char smem[];
    const uint32_t sb = smem_u32(smem);
    const int tid  = threadIdx.x;
    const int wid  = tid >> 5, lane = tid & 31;
    const int wM   = wid >> 1;
    const int wN   = wid & 1;
    const int m0   = blockIdx.y << 7;
    const int j0   = blockIdx.x << 5;

    const char* gAh = (const char*)(Ahi + (size_t)m0 * KDIM);
    const char* gW  = (const char*)W;

    int srow[4], soff[4]; uint32_t sso[4];
#pragma unroll
    for (int q = 0; q < 4; q++) {
        int id = tid * 4 + q;
        srow[q] = id >> 3;
        soff[q] = (id & 7) << 4;
        sso[q]  = (uint32_t)((srow[q] << 7) | (soff[q] ^ ((srow[q] & 7) << 4)));
    }
    int bgr[3], boff[3]; uint32_t bso[3];
#pragma unroll
    for (int q = 0; q < 3; q++) {
        int id = tid * 3 + q;
        int rb = id >> 3;
        boff[q] = (id & 7) << 4;
        bgr[q]  = j0 + (rb & 31) + (rb >> 5) * 512;
        bso[q]  = (uint32_t)((rb << 7) | (boff[q] ^ ((rb & 7) << 4)));
    }

    const int lr16 = lane & 15;
    const int lhi  = (lane >> 4) << 4;
    uint32_t aBase[2], aXr[2];
#pragma unroll
    for (int mt = 0; mt < 2; mt++) {
        int r = wM * 32 + mt * 16 + lr16;
        aBase[mt] = (uint32_t)(r << 7);
        aXr[mt]   = ((r & 7) << 4);
    }
    uint32_t bBase[3], bXr[3];
#pragma unroll
    for (int g = 0; g < 3; g++) {
        int r = wN * 16 + g * 32 + lr16;
        bBase[g] = (uint32_t)(r << 7);
        bXr[g]   = ((r & 7) << 4);
    }

    float acc[2][3][2][4];
#pragma unroll
    for (int i = 0; i < 2; i++)
#pragma unroll
        for (int g = 0; g < 3; g++)
#pragma unroll
            for (int a = 0; a < 2; a++)
#pragma unroll
                for (int v = 0; v < 4; v++) acc[i][g][a][v] = 0.f;

    auto load_chunk = [&](int s, int c) {
        const uint32_t st = sb + s * 28672;
        const int cb = c * 128;
#pragma unroll
        for (int q = 0; q < 4; q++) {
            int go = srow[q] * 1024 + cb + soff[q];
            cpasync16(st + sso[q], gAh + go);
        }
#pragma unroll
        for (int q = 0; q < 3; q++) {
            int go = bgr[q] * 1024 + cb + boff[q];
            cpasync16(st + 16384 + bso[q], gW + go);
        }
        cp_commit();
    };

    load_chunk(0, 0);
    load_chunk(1, 1);

#pragma unroll
    for (int c = 0; c < NCH; c++) {
        const int s = c % 3;
        if (c + 2 < NCH) { load_chunk((c + 2) % 3, c + 2); cp_wait<2>(); }
        else if (c + 1 < NCH) cp_wait<1>();
        else                  cp_wait<0>();
        __syncthreads();

        const uint32_t stA0 = sb + s * 28672;
        const uint32_t stB0 = stA0 + 16384;

#pragma unroll
        for (int k16 = 0; k16 < 4; k16++) {
            const uint32_t ko = (uint32_t)(k16 * 32 + lhi);
            uint32_t ah[2][4];
#pragma unroll
            for (int mt = 0; mt < 2; mt++)
                ldsm4(ah[mt][0], ah[mt][1], ah[mt][2], ah[mt][3],
                      stA0 + aBase[mt] + (ko ^ aXr[mt]));
            uint32_t bh[3][4];
#pragma unroll
            for (int g = 0; g < 3; g++)
                ldsm4(bh[g][0], bh[g][1], bh[g][2], bh[g][3],
                      stB0 + bBase[g] + (ko ^ bXr[g]));
#pragma unroll
            for (int mt = 0; mt < 2; mt++)
#pragma unroll
                for (int g = 0; g < 3; g++) {
                    hmma16816(acc[mt][g][0], ah[mt], bh[g][0], bh[g][2]);
                    hmma16816(acc[mt][g][1], ah[mt], bh[g][1], bh[g][3]);
                }
        }
        __syncthreads();
    }

    const int lr = lane >> 2;
    const int lc = (lane & 3) << 1;
#pragma unroll
    for (int mt = 0; mt < 2; mt++) {
        const int mBase = m0 + wM * 32 + mt * 16 + lr;
#pragma unroll
        for (int a = 0; a < 2; a++) {
            const int j = j0 + wN * 16 + a * 8 + lc;
            const float2 bR = *(const float2*)(bhh + j);
            const float2 bZ = *(const float2*)(bhh + 512 + j);
            const float2 bN = *(const float2*)(bhh + 1024 + j);
#pragma unroll
            for (int hh = 0; hh < 2; hh++) {
                const int row = mBase + hh * 8;
                const int vi = hh * 2;
                float2 gR, gZ, gN;
                if (GIMODE == 1) {
                    const float* gi = (const float*)GIt + j;
                    gR = *(const float2*)(gi);
                    gZ = *(const float2*)(gi + 512);
                    gN = *(const float2*)(gi + 1024);
                } else {
                    const __half* gi;
                    if (GIMODE == 0)
                        gi = (const __half*)GIt + (size_t)row * H3 + j;
                    else {
                        int tok = gt[row * Tn + (step - 2)];
                        gi = (const __half*)GIt + (size_t)tok * H3 + j;
                    }
                    gR = __half22float2(*(const __half2*)(gi));
                    gZ = __half22float2(*(const __half2*)(gi + 512));
                    gN = __half22float2(*(const __half2*)(gi + 1024));
                }
                float2 hp = __half22float2(
                    *(const __half2*)(Ahi + (size_t)row * Hn + j));
                float r0 = sigf(gR.x + acc[mt][0][a][vi]     + bR.x);
                float r1 = sigf(gR.y + acc[mt][0][a][vi + 1] + bR.y);
                float z0 = sigf(gZ.x + acc[mt][1][a][vi]     + bZ.x);
                float z1 = sigf(gZ.y + acc[mt][1][a][vi + 1] + bZ.y);
                float n0 = tanhf(gN.x + r0 * (acc[mt][2][a][vi]     + bN.x));
                float n1 = tanhf(gN.y + r1 * (acc[mt][2][a][vi + 1] + bN.y));
                float h0 = (1.f - z0) * n0 + z0 * hp.x;
                float h1 = (1.f - z1) * n1 + z1 * hp.y;
                size_t oh = (size_t)row * Hn + j;
                if (houtF) *(float2*)(houtF + oh) = make_float2(h0, h1);
                *(__half2*)(hi + oh) = __floats2half2_rn(h0, h1);
            }
        }
    }
}

// ---------------------------------------------------------------------------
// MERGED step for layers 1/2: K-concatenated GH+GI, fp16 carried state.
// Chunks 0-7: A = h_{t-1}, B = Whh. Chunks 8-15: A = x, B = Wih.
// r/z combined accumulators; n split into n_h / n_i. Optional fp32 out.
// ---------------------------------------------------------------------------
__global__ void __launch_bounds__(256, 2)
gru_step2(const __half* __restrict__ Ah, const __half* __restrict__ Ax,
          const __half* __restrict__ Whh, const __half* __restrict__ Wih,
          const float* __restrict__ bhh, const float* __restrict__ bih,
          float* __restrict__ houtF, __half* __restrict__ hi)
{
    extern __shared__ __align__(128) char smem[];
    const uint32_t sb = smem_u32(smem);
    const int tid  = threadIdx.x;
    const int wid  = tid >> 5, lane = tid & 31;
    const int wM   = wid >> 1;
    const int wN   = wid & 1;
    const int m0   = blockIdx.y << 7;
    const int j0   = blockIdx.x << 5;

    const char* gAh = (const char*)(Ah + (size_t)m0 * KDIM);
    const char* gAx = (const char*)(Ax + (size_t)m0 * KDIM);
    const char* gWh = (const char*)Whh;
    const char* gWi = (const char*)Wih;

    int srow[4], soff[4]; uint32_t sso[4];
#pragma unroll
    for (int q = 0; q < 4; q++) {
        int id = tid * 4 + q;
        srow[q] = id >> 3;
        soff[q] = (id & 7) << 4;
        sso[q]  = (uint32_t)((srow[q] << 7) | (soff[q] ^ ((srow[q] & 7) << 4)));
    }
    int bgr[3], boff[3]; uint32_t bso[3];
#pragma unroll
    for (int q = 0; q < 3; q++) {
        int id = tid * 3 + q;
        int rb = id >> 3;
        boff[q] = (id & 7) << 4;
        bgr[q]  = j0 + (rb & 31) + (rb >> 5) * 512;
        bso[q]  = (uint32_t)((rb << 7) | (boff[q] ^ ((rb & 7) << 4)));
    }

    const int lr16 = lane & 15;
    const int lhi  = (lane >> 4) << 4;
    uint32_t aBase[2], aXr[2];
#pragma unroll
    for (int mt = 0; mt < 2; mt++) {
        int r = wM * 32 + mt * 16 + lr16;
        aBase[mt] = (uint32_t)(r << 7);
        aXr[mt]   = ((r & 7) << 4);
    }
    uint32_t bBase[3], bXr[3];
#pragma unroll
    for (int g = 0; g < 3; g++) {
        int r = wN * 16 + g * 32 + lr16;
        bBase[g] = (uint32_t)(r << 7);
        bXr[g]   = ((r & 7) << 4);
    }

    // acc groups: 0=r (combined), 1=z (combined), 2=n_h, 3=n_i
    float acc[2][4][2][4];
#pragma unroll
    for (int i = 0; i < 2; i++)
#pragma unroll
        for (int g = 0; g < 4; g++)
#pragma unroll
            for (int a = 0; a < 2; a++)
#pragma unroll
                for (int v = 0; v < 4; v++) acc[i][g][a][v] = 0.f;

    auto load_chunk = [&](int s, int c) {
        const uint32_t st = sb + s * 28672;
        const char* gA = (c < NCH) ? gAh : gAx;
        const char* gW = (c < NCH) ? gWh : gWi;
        const int cb = (c & 7) * 128;
#pragma unroll
        for (int q = 0; q < 4; q++) {
            int go = srow[q] * 1024 + cb + soff[q];
            cpasync16(st + sso[q], gA + go);
        }
#pragma unroll
        for (int q = 0; q < 3; q++) {
            int go = bgr[q] * 1024 + cb + boff[q];
            cpasync16(st + 16384 + bso[q], gW + go);
        }
        cp_commit();
    };

    load_chunk(0, 0);
    load_chunk(1, 1);

#pragma unroll
    for (int c = 0; c < 2 * NCH; c++) {
        const int s = c % 3;
        if (c + 2 < 2 * NCH) { load_chunk((c + 2) % 3, c + 2); cp_wait<2>(); }
        else if (c + 1 < 2 * NCH) cp_wait<1>();
        else                      cp_wait<0>();
        __syncthreads();

        const uint32_t stA0 = sb + s * 28672;
        const uint32_t stB0 = stA0 + 16384;
        const int ng = (c < NCH) ? 2 : 3;

#pragma unroll
        for (int k16 = 0; k16 < 4; k16++) {
            const uint32_t ko = (uint32_t)(k16 * 32 + lhi);
            uint32_t ah[2][4];
#pragma unroll
            for (int mt = 0; mt < 2; mt++)
                ldsm4(ah[mt][0], ah[mt][1], ah[mt][2], ah[mt][3],
                      stA0 + aBase[mt] + (ko ^ aXr[mt]));
            uint32_t bh[3][4];
#pragma unroll
            for (int g = 0; g < 3; g++)
                ldsm4(bh[g][0], bh[g][1], bh[g][2], bh[g][3],
                      stB0 + bBase[g] + (ko ^ bXr[g]));
#pragma unroll
            for (int mt = 0; mt < 2; mt++) {
                hmma16816(acc[mt][0][0], ah[mt], bh[0][0], bh[0][2]);
                hmma16816(acc[mt][0][1], ah[mt], bh[0][1], bh[0][3]);
                hmma16816(acc[mt][1][0], ah[mt], bh[1][0], bh[1][2]);
                hmma16816(acc[mt][1][1], ah[mt], bh[1][1], bh[1][3]);
                hmma16816(acc[mt][ng][0], ah[mt], bh[2][0], bh[2][2]);
                hmma16816(acc[mt][ng][1], ah[mt], bh[2][1], bh[2][3]);
            }
        }
        __syncthreads();
    }

    const int lr = lane >> 2;
    const int lc = (lane & 3) << 1;
#pragma unroll
    for (int mt = 0; mt < 2; mt++) {
        const int mBase = m0 + wM * 32 + mt * 16 + lr;
#pragma unroll
        for (int a = 0; a < 2; a++) {
            const int j = j0 + wN * 16 + a * 8 + lc;
            const float2 bhR = *(const float2*)(bhh + j);
            const float2 bhZ = *(const float2*)(bhh + 512 + j);
            const float2 bhN = *(const float2*)(bhh + 1024 + j);
            const float2 biR = *(const float2*)(bih + j);
            const float2 biZ = *(const float2*)(bih + 512 + j);
            const float2 biN = *(const float2*)(bih + 1024 + j);
#pragma unroll
            for (int hh = 0; hh < 2; hh++) {
                const int row = mBase + hh * 8;
                const int vi = hh * 2;
                float2 hp = __half22float2(
                    *(const __half2*)(Ah + (size_t)row * Hn + j));
                float r0 = sigf(acc[mt][0][a][vi]     + bhR.x + biR.x);
                float r1 = sigf(acc[mt][0][a][vi + 1] + bhR.y + biR.y);
                float z0 = sigf(acc[mt][1][a][vi]     + bhZ.x + biZ.x);
                float z1 = sigf(acc[mt][1][a][vi + 1] + bhZ.y + biZ.y);
                float n0 = tanhf(acc[mt][3][a][vi]     + biN.x
                                 + r0 * (acc[mt][2][a][vi]     + bhN.x));
                float n1 = tanhf(acc[mt][3][a][vi + 1] + biN.y
                                 + r1 * (acc[mt][2][a][vi + 1] + bhN.y));
                float h0 = (1.f - z0) * n0 + z0 * hp.x;
                float h1 = (1.f - z1) * n1 + z1 * hp.y;
                size_t oh = (size_t)row * Hn + j;
                if (houtF) *(float2*)(houtF + oh) = make_float2(h0, h1);
                *(__half2*)(hi + oh) = __floats2half2_rn(h0, h1);
            }
        }
    }
}

// ---------------- elementwise kernels ----------------
__global__ void convW(const float* __restrict__ W_ih, const float* __restrict__ W_hh,
                      const float* __restrict__ W_out, const float* __restrict__ W_tp,
                      const float* __restrict__ emb,
                      __half* __restrict__ wih, __half* __restrict__ whh,
                      __half* __restrict__ wo,  __half* __restrict__ wt,
                      __half* __restrict__ embh, __half* __restrict__ embl)
{
    int i = blockIdx.x * blockDim.x + threadIdx.x;
    if (i >= 1376256) return;
    if (i < 1310720) {
        const float* s; __half* d; int j;
        if (i < 589824)       { s = W_ih;  d = wih; j = i; }
        else if (i < 1179648) { s = W_hh;  d = whh; j = i - 589824; }
        else if (i < 1245184) { s = W_out; d = wo;  j = i - 1179648; }
        else                  { s = W_tp;  d = wt;  j = i - 1245184; }
        float4 v = ((const float4*)s)[j];
        ((__half2*)d)[2 * j + 0] = __floats2half2_rn(v.x, v.y);
        ((__half2*)d)[2 * j + 1] = __floats2half2_rn(v.z, v.w);
    } else {
        int j = i - 1310720;
        float4 v = ((const float4*)emb)[j];
        __half h0, h1, h2, h3, l0, l1, l2, l3;
        split1h(v.x, h0, l0); split1h(v.y, h1, l1);
        split1h(v.z, h2, l2); split1h(v.w, h3, l3);
        ((__half2*)embh)[2 * j + 0] = __halves2half2(h0, h1);
        ((__half2*)embh)[2 * j + 1] = __halves2half2(h2, h3);
        ((__half2*)embl)[2 * j + 0] = __halves2half2(l0, l1);
        ((__half2*)embl)[2 * j + 1] = __halves2half2(l2, l3);
    }
}

__global__ void prep_kernel(const float* __restrict__ prev,
                            const float* __restrict__ action,
                            const float* __restrict__ W_a, const float* __restrict__ b_a,
                            __half* __restrict__ pqh,
                            __half* __restrict__ x0h, __half* __restrict__ x0l)
{
    const int NPREV = (int)(Ln * BH / 4);
    int i = blockIdx.x * blockDim.x + threadIdx.x;
    if (i < NPREV) {
        float4 v = ((const float4*)prev)[i];
        ((__half2*)pqh)[2 * i + 0] = __floats2half2_rn(v.x, v.y);
        ((__half2*)pqh)[2 * i + 1] = __floats2half2_rn(v.z, v.w);
    } else if (i < NPREV + (int)(BH / 4)) {
        int j = i - NPREV;
        int e0 = j * 4;
        int b = e0 >> 9, c = e0 & 511;
        float a0 = action[b * 3 + 0], a1 = action[b * 3 + 1], a2 = action[b * 3 + 2];
        __half hs[4], ls[4];
#pragma unroll
        for (int q = 0; q < 4; q++) {
            int jj = c + q;
            float s = b_a[jj] + a0 * W_a[jj * 3 + 0] + a1 * W_a[jj * 3 + 1]
                              + a2 * W_a[jj * 3 + 2];
            split1h(s, hs[q], ls[q]);
        }
        ((__half2*)x0h)[2 * j + 0] = __halves2half2(hs[0], hs[1]);
        ((__half2*)x0h)[2 * j + 1] = __halves2half2(hs[2], hs[3]);
        ((__half2*)x0l)[2 * j + 0] = __halves2half2(ls[0], ls[1]);
        ((__half2*)x0l)[2 * j + 1] = __halves2half2(ls[2], ls[3]);
    }
}

__global__ void split2_kernel(const float* __restrict__ src,
                              __half* __restrict__ hi, __half* __restrict__ lo, int n4)
{
    int i = blockIdx.x * blockDim.x + threadIdx.x;
    if (i >= n4) return;
    float4 v = ((const float4*)src)[i];
    __half h0, h1, h2, h3, l0, l1, l2, l3;
    split1h(v.x, h0, l0); split1h(v.y, h1, l1);
    split1h(v.z, h2, l2); split1h(v.w, h3, l3);
    ((__half2*)hi)[2 * i + 0] = __halves2half2(h0, h1);
    ((__half2*)hi)[2 * i + 1] = __halves2half2(h2, h3);
    ((__half2*)lo)[2 * i + 0] = __halves2half2(l0, l1);
    ((__half2*)lo)[2 * i + 1] = __halves2half2(l2, l3);
}

// heads from fp16 h2 (layer-2 output at slot 0)
__global__ void heads_kernel(const __half* __restrict__ h2, const float* __restrict__ W_r,
                             const float* __restrict__ b_r, const float* __restrict__ W_d,
                             const float* __restrict__ b_d,
                             float* __restrict__ outr, float* __restrict__ outd)
{
    int gw = (blockIdx.x * blockDim.x + threadIdx.x) >> 5;
    int lane = threadIdx.x & 31;
    if (gw >= Bsz) return;
    const __half* hb = h2 + (size_t)gw * Hn;
    float sr = 0.f, sd = 0.f;
#pragma unroll
    for (int k = lane; k < Hn; k += 32) {
        float v = __half2float(hb[k]);
        sr = fmaf(v, W_r[k], sr);
        sd = fmaf(v, W_d[k], sd);
    }
#pragma unroll
    for (int o = 16; o > 0; o >>= 1) {
        sr += __shfl_down_sync(0xffffffffu, sr, o);
        sd += __shfl_down_sync(0xffffffffu, sd, o);
    }
    if (lane == 0) { outr[gw] = sr + b_r[0]; outd[gw] = sd + b_d[0]; }
}

// ---------------------------------------------------------------------------
extern "C" void kernel_launch(void* const* d_in, const int* in_sizes, int n_in,
                              void* d_out, int out_size)
{
    const float* action      = (const float*)d_in[0];
    const float* prev_hidden = (const float*)d_in[1];
    const int*   gt          = (const int*)d_in[2];
    const float* W_a         = (const float*)d_in[3];
    const float* b_a         = (const float*)d_in[4];
    const float* emb         = (const float*)d_in[5];
    const float* W_tp        = (const float*)d_in[6];
    const float* b_tp        = (const float*)d_in[7];
    const float* W_ih        = (const float*)d_in[8];
    const float* W_hh        = (const float*)d_in[9];
    const float* b_ih        = (const float*)d_in[10];
    const float* b_hh        = (const float*)d_in[11];
    const float* W_out       = (const float*)d_in[12];
    const float* b_out       = (const float*)d_in[13];
    const float* W_r         = (const float*)d_in[14];
    const float* b_r         = (const float*)d_in[15];
    const float* W_d         = (const float*)d_in[16];
    const float* b_d         = (const float*)d_in[17];
    float* out = (float*)d_out;

    static cudaStream_t sL1 = nullptr, sL2 = nullptr, sLg = nullptr;
    static cudaEvent_t evL0[NSTEP], evL1[NSTEP], evL2[NSTEP], evLg[NSTEP];
    static cudaEvent_t evPre, evGtab;
    if (!sL1) {
        int loPri, hiPri;
        cudaDeviceGetStreamPriorityRange(&loPri, &hiPri);
        int midPri = (hiPri + 1 <= loPri) ? hiPri + 1 : loPri;
        // L1 highest among side streams, then L2, logits lowest
        cudaStreamCreateWithPriority(&sL1, cudaStreamNonBlocking, hiPri);
        cudaStreamCreateWithPriority(&sL2, cudaStreamNonBlocking, midPri);
        cudaStreamCreateWithPriority(&sLg, cudaStreamNonBlocking, loPri);
        for (int i = 0; i < NSTEP; i++) {
            cudaEventCreateWithFlags(&evL0[i], cudaEventDisableTiming);
            cudaEventCreateWithFlags(&evL1[i], cudaEventDisableTiming);
            cudaEventCreateWithFlags(&evL2[i], cudaEventDisableTiming);
            cudaEventCreateWithFlags(&evLg[i], cudaEventDisableTiming);
        }
        cudaEventCreateWithFlags(&evPre, cudaEventDisableTiming);
        cudaEventCreateWithFlags(&evGtab, cudaEventDisableTiming);
        cudaFuncSetAttribute((const void*)gemm_h2<0, 2, 0>, cudaFuncAttributeMaxDynamicSharedMemorySize, GEMM_SMEM2);
        cudaFuncSetAttribute((const void*)gemm_h2<0, 2, 1>, cudaFuncAttributeMaxDynamicSharedMemorySize, GEMM_SMEM2);
        cudaFuncSetAttribute((const void*)gemm_h2<3, 1, 0>, cudaFuncAttributeMaxDynamicSharedMemorySize, GEMM_SMEM1);
        cudaFuncSetAttribute((const void*)gru_step<0>, cudaFuncAttributeMaxDynamicSharedMemorySize, STEP_SMEM);
        cudaFuncSetAttribute((const void*)gru_step<1>, cudaFuncAttributeMaxDynamicSharedMemorySize, STEP_SMEM);
        cudaFuncSetAttribute((const void*)gru_step<2>, cudaFuncAttributeMaxDynamicSharedMemorySize, STEP_SMEM);
        cudaFuncSetAttribute((const void*)gru_step2, cudaFuncAttributeMaxDynamicSharedMemorySize, STEP_SMEM);
    }

    __half *u0, *u1, *u2, *x0h, *x0l, *pqh;
    __half *wih, *whh, *wo, *wt, *embh, *embl, *Pqh, *Pql, *GIh, *Gtabh;
    float *P;
    cudaGetSymbolAddress((void**)&u0, g_u0);
    cudaGetSymbolAddress((void**)&u1, g_u1);
    cudaGetSymbolAddress((void**)&u2, g_u2);
    cudaGetSymbolAddress((void**)&x0h, g_x0h);   cudaGetSymbolAddress((void**)&x0l, g_x0l);
    cudaGetSymbolAddress((void**)&pqh, g_pq_hi);
    cudaGetSymbolAddress((void**)&wih, g_wih);   cudaGetSymbolAddress((void**)&whh, g_whh);
    cudaGetSymbolAddress((void**)&wo,  g_wo);    cudaGetSymbolAddress((void**)&wt,  g_wt);
    cudaGetSymbolAddress((void**)&embh, g_embh); cudaGetSymbolAddress((void**)&embl, g_embl);
    cudaGetSymbolAddress((void**)&Pqh, g_Pqh);   cudaGetSymbolAddress((void**)&Pql, g_Pql);
    cudaGetSymbolAddress((void**)&GIh, g_GIh);
    cudaGetSymbolAddress((void**)&P, g_P);
    cudaGetSymbolAddress((void**)&Gtabh, g_Gtabh);

    float* outLogits = out;
    float* outReward = out + (size_t)Bsz * Tn * Cn;
    float* outDone   = outReward + Bsz;
    float* outFinal  = outDone + Bsz;

    const dim3 stepGrid(16, 32);

    // ---- preamble (main stream) ----
    convW<<<(1376256 + 255) / 256, 256>>>(W_ih, W_hh, W_out, W_tp, emb,
                                          wih, whh, wo, wt, embh, embl);
    prep_kernel<<<((int)(Ln * BH / 4 + BH / 4) + 255) / 256, 256>>>(
        prev_hidden, action, W_a, b_a, pqh, x0h, x0l);
    gemm_h2<0, 2, 1><<<dim3(12, 32), 256, GEMM_SMEM2>>>(x0h, x0l, wih, b_ih, GIh, H3);
    cudaEventRecord(evPre, 0);

    // P / Gtab chain on side stream (overlaps L0 t=0..1)
    cudaStreamWaitEvent(sLg, evPre, 0);
    gemm_h2<0, 2, 0><<<dim3(4, 4), 256, GEMM_SMEM2, sLg>>>(embh, embl, wt, b_tp, P, Hn);
    split2_kernel<<<((Cn * Hn / 4) + 255) / 256, 256, 0, sLg>>>(P, Pqh, Pql, Cn * Hn / 4);
    gemm_h2<0, 2, 1><<<dim3(12, 4), 256, GEMM_SMEM2, sLg>>>(Pqh, Pql, wih, b_ih, Gtabh, H3);
    cudaEventRecord(evGtab, sLg);

    // ---- layer 0 recurrence on main stream (fp16 carried state) ----
    for (int t = 0; t < NSTEP; t++) {
        if (t == 2) cudaStreamWaitEvent(0, evGtab, 0);
        const __half* ph = t ? (u0 + (size_t)(t - 1) * BH) : pqh;
        float* hF = (t == 16) ? outFinal : nullptr;
        __half* oh = u0 + (size_t)t * BH;
        if (t == 0)
            gru_step<0><<<stepGrid, 256, STEP_SMEM>>>(ph, whh, b_hh,
                                                      GIh, gt, t, hF, oh);
        else if (t == 1)
            gru_step<1><<<stepGrid, 256, STEP_SMEM>>>(ph, whh, b_hh,
                                                      b_ih, gt, t, hF, oh);
        else
            gru_step<2><<<stepGrid, 256, STEP_SMEM>>>(ph, whh, b_hh,
                                                      Gtabh, gt, t, hF, oh);
        cudaEventRecord(evL0[t], 0);
    }

    // ---- layer 1 recurrence on sL1 (merged GI+GH steps) ----
    for (int t = 0; t < NSTEP; t++) {
        cudaStreamWaitEvent(sL1, evL0[t], 0);
        const __half* ph = t ? (u1 + (size_t)(t - 1) * BH) : (pqh + BH);
        float* hF = (t == 16) ? (outFinal + BH) : nullptr;
        gru_step2<<<stepGrid, 256, STEP_SMEM, sL1>>>(
            ph, u0 + (size_t)t * BH,
            whh + (size_t)1 * H3 * Hn, wih + (size_t)1 * H3 * Hn,
            b_hh + 1 * H3, b_ih + 1 * H3,
            hF, u1 + (size_t)t * BH);
        cudaEventRecord(evL1[t], sL1);
    }

    // ---- layer 2 recurrence on sL2 (merged GI+GH steps) ----
    for (int t = 0; t < NSTEP; t++) {
        cudaStreamWaitEvent(sL2, evL1[t], 0);
        const __half* ph = t ? (u2 + (size_t)(t - 1) * BH) : (pqh + 2 * BH);
        float* hF = (t == 16) ? (outFinal + 2 * BH) : nullptr;
        gru_step2<<<stepGrid, 256, STEP_SMEM, sL2>>>(
            ph, u1 + (size_t)t * BH,
            whh + (size_t)2 * H3 * Hn, wih + (size_t)2 * H3 * Hn,
            b_hh + 2 * H3, b_ih + 2 * H3,
            hF, u2 + (size_t)t * BH);
        cudaEventRecord(evL2[t], sL2);
    }

    // ---- logits chunks: t=1..15 on sLg; final (critical-tail) chunk on sL1 ----
    for (int t = 1; t < NSTEP - 1; t++) {
        cudaStreamWaitEvent(sLg, evL2[t], 0);
        gemm_h2<3, 1, 0><<<dim3(4, 32), 256, GEMM_SMEM1, sLg>>>(
            u2 + (size_t)t * BH, nullptr, wo, b_out, outLogits, t - 1);
        cudaEventRecord(evLg[t], sLg);
    }
    {
        const int t = NSTEP - 1;   // 16
        cudaStreamWaitEvent(sL1, evL2[t], 0);
        gemm_h2<3, 1, 0><<<dim3(4, 32), 256, GEMM_SMEM1, sL1>>>(
            u2 + (size_t)t * BH, nullptr, wo, b_out, outLogits, t - 1);
        cudaEventRecord(evLg[t], sL1);
    }

    // ---- epilogue on main stream ----
    cudaStreamWaitEvent(0, evL2[0], 0);
    heads_kernel<<<(Bsz * 32 + 255) / 256, 256>>>(
        u2, W_r, b_r, W_d, b_d, outReward, outDone);
    cudaStreamWaitEvent(0, evL1[16], 0);
    cudaStreamWaitEvent(0, evL2[16], 0);
    for (int t = 1; t < NSTEP; t++)
        cudaStreamWaitEvent(0, evLg[t], 0);
}

// round 17
// speedup vs baseline: 1.0145x; 1.0145x over previous
#include <cuda_runtime.h>
#include <cuda_fp16.h>
#include <cstdint>
#include <math.h>

// ---------------- problem constants ----------------
#define Bsz   4096
#define Hn    512
#define H3    1536
#define Ln    3
#define Tn    16
#define Cn    512
#define NSTEP 17
#define KDIM  512
#define NCH   8            // K chunks of 64 fp16 (128B rows)

static const size_t BH  = (size_t)Bsz * Hn;
static const size_t BH3 = (size_t)Bsz * H3;

// ---------------- persistent device scratch ----------------
__device__ __align__(128) __half g_u0[(size_t)NSTEP * Bsz * Hn];
__device__ __align__(128) __half g_u1[(size_t)NSTEP * Bsz * Hn];
__device__ __align__(128) __half g_u2[(size_t)NSTEP * Bsz * Hn];
__device__ __align__(128) __half g_x0h[(size_t)Bsz * Hn];
__device__ __align__(128) __half g_pq_hi[(size_t)Ln * Bsz * Hn];
__device__ __align__(128) __half g_wih[(size_t)Ln * H3 * Hn];
__device__ __align__(128) __half g_whh[(size_t)Ln * H3 * Hn];
__device__ __align__(128) __half g_wo[(size_t)Cn * Hn];
__device__ __align__(128) __half g_wt[(size_t)Hn * Hn];
__device__ __align__(128) __half g_embh[(size_t)Cn * Hn];
__device__ __align__(128) __half g_embl[(size_t)Cn * Hn];
__device__ __align__(128) float  g_P[(size_t)Cn * Hn];
__device__ __align__(128) __half g_Pqh[(size_t)Cn * Hn];
__device__ __align__(128) __half g_Pql[(size_t)Cn * Hn];
__device__ __align__(128) __half g_Gtabh[(size_t)Cn * H3];

// ---------------- PTX helpers ----------------
__device__ __forceinline__ uint32_t smem_u32(const void* p) {
    uint32_t a;
    asm("{ .reg .u64 t; cvta.to.shared.u64 t, %1; cvt.u32.u64 %0, t; }" : "=r"(a) : "l"(p));
    return a;
}
__device__ __forceinline__ void cpasync16(uint32_t s, const void* g) {
    asm volatile("cp.async.cg.shared.global [%0], [%1], 16;" :: "r"(s), "l"(g));
}
__device__ __forceinline__ void cp_commit() {
    asm volatile("cp.async.commit_group;" ::: "memory");
}
template <int N> __device__ __forceinline__ void cp_wait() {
    asm volatile("cp.async.wait_group %0;" :: "n"(N) : "memory");
}
__device__ __forceinline__ void ldsm4(uint32_t& r0, uint32_t& r1, uint32_t& r2, uint32_t& r3,
                                      uint32_t addr) {
    asm volatile("ldmatrix.sync.aligned.m8n8.x4.shared.b16 {%0,%1,%2,%3}, [%4];"
                 : "=r"(r0), "=r"(r1), "=r"(r2), "=r"(r3) : "r"(addr));
}
__device__ __forceinline__ void hmma16816(float* d, const uint32_t* a, uint32_t b0, uint32_t b1) {
    asm volatile(
        "mma.sync.aligned.m16n8k16.row.col.f32.f16.f16.f32 "
        "{%0,%1,%2,%3}, {%4,%5,%6,%7}, {%8,%9}, {%0,%1,%2,%3};"
        : "+f"(d[0]), "+f"(d[1]), "+f"(d[2]), "+f"(d[3])
        : "r"(a[0]), "r"(a[1]), "r"(a[2]), "r"(a[3]), "r"(b0), "r"(b1));
}

#define GEMM_SMEM2 (2 * 49152)
#define GEMM_SMEM1 (2 * 32768)
#define STEP_SMEM  (3 * 28672)   // step kernels: 3-stage pipeline

__device__ __forceinline__ float sigf(float x) { return 1.f / (1.f + __expf(-x)); }
__device__ __forceinline__ void split1h(float x, __half& h, __half& l) {
    h = __float2half_rn(x);
    l = __float2half_rn(x - __half2float(h));
}

// ---------------------------------------------------------------------------
// fp16 GEMM, 128x128 tile. PLANES: A planes. OUTH: 1 => fp16 C.
// MODE 0: row-major C (ld = ldc_or_slot).
// MODE 3: logits chunk: C[b, slot, n] fp32, slot = ldc_or_slot.
// ---------------------------------------------------------------------------
template <int MODE, int PLANES, int OUTH>
__global__ void __launch_bounds__(256, 2)
gemm_h2(const __half* __restrict__ Ahi, const __half* __restrict__ Alo,
        const __half* __restrict__ Bh,
        const float* __restrict__ bias, void* __restrict__ Cv, int ldc_or_slot)
{
    constexpr int STAGE = (PLANES == 2) ? 49152 : 32768;
    constexpr int BOFF  = PLANES * 16384;
    extern __shared__ __align__(128) char smem[];
    const uint32_t sb = smem_u32(smem);
    const int tid  = threadIdx.x;
    const int wid  = tid >> 5, lane = tid & 31;
    const int wM   = wid >> 1;
    const int wN   = wid & 1;
    const int m0   = blockIdx.y << 7, n0 = blockIdx.x << 7;

    const char* gAh = (const char*)(Ahi + (size_t)m0 * KDIM);
    const char* gAl = (const char*)(Alo + (size_t)m0 * KDIM);
    const char* gB  = (const char*)(Bh  + (size_t)n0 * KDIM);

    int srow[4], soff[4]; uint32_t sso[4];
#pragma unroll
    for (int q = 0; q < 4; q++) {
        int id = tid * 4 + q;
        srow[q] = id >> 3;
        soff[q] = (id & 7) << 4;
        sso[q]  = (uint32_t)((srow[q] << 7) | (soff[q] ^ ((srow[q] & 7) << 4)));
    }

    const int lr16 = lane & 15;
    const int lhi  = (lane >> 4) << 4;
    uint32_t aBase[2], aXr[2];
#pragma unroll
    for (int mt = 0; mt < 2; mt++) {
        int r = wM * 32 + mt * 16 + lr16;
        aBase[mt] = (uint32_t)(r << 7);
        aXr[mt]   = ((r & 7) << 4);
    }
    uint32_t bBase[4], bXr[4];
#pragma unroll
    for (int nt = 0; nt < 4; nt++) {
        int r = wN * 64 + nt * 16 + lr16;
        bBase[nt] = (uint32_t)(r << 7);
        bXr[nt]   = ((r & 7) << 4);
    }

    float acc[2][8][4];
#pragma unroll
    for (int i = 0; i < 2; i++)
#pragma unroll
        for (int j = 0; j < 8; j++)
#pragma unroll
            for (int v = 0; v < 4; v++) acc[i][j][v] = 0.f;

    auto load_chunk = [&](int s, int c) {
        const uint32_t st = sb + s * STAGE;
        const int cb = c * 128;
#pragma unroll
        for (int q = 0; q < 4; q++) {
            int go = srow[q] * 1024 + cb + soff[q];
            cpasync16(st + sso[q], gAh + go);
            if (PLANES == 2) cpasync16(st + 16384 + sso[q], gAl + go);
            cpasync16(st + BOFF + sso[q], gB + go);
        }
        cp_commit();
    };

    load_chunk(0, 0);

    for (int c = 0; c < NCH; c++) {
        const int s = c & 1;
        if (c + 1 < NCH) { load_chunk(s ^ 1, c + 1); cp_wait<1>(); }
        else             { cp_wait<0>(); }
        __syncthreads();

        const uint32_t stA0 = sb + s * STAGE;
        const uint32_t stA1 = stA0 + 16384;
        const uint32_t stB0 = stA0 + BOFF;

#pragma unroll
        for (int k16 = 0; k16 < 4; k16++) {
            const uint32_t ko = (uint32_t)(k16 * 32 + lhi);
            uint32_t ah[2][4], al[2][4];
#pragma unroll
            for (int mt = 0; mt < 2; mt++) {
                ldsm4(ah[mt][0], ah[mt][1], ah[mt][2], ah[mt][3],
                      stA0 + aBase[mt] + (ko ^ aXr[mt]));
                if (PLANES == 2)
                    ldsm4(al[mt][0], al[mt][1], al[mt][2], al[mt][3],
                          stA1 + aBase[mt] + (ko ^ aXr[mt]));
            }
            uint32_t bh[4][4];
#pragma unroll
            for (int nt = 0; nt < 4; nt++)
                ldsm4(bh[nt][0], bh[nt][1], bh[nt][2], bh[nt][3],
                      stB0 + bBase[nt] + (ko ^ bXr[nt]));
#pragma unroll
            for (int mt = 0; mt < 2; mt++)
#pragma unroll
                for (int nt = 0; nt < 4; nt++) {
                    hmma16816(acc[mt][2 * nt + 0], ah[mt], bh[nt][0], bh[nt][2]);
                    hmma16816(acc[mt][2 * nt + 1], ah[mt], bh[nt][1], bh[nt][3]);
                    if (PLANES == 2) {
                        hmma16816(acc[mt][2 * nt + 0], al[mt], bh[nt][0], bh[nt][2]);
                        hmma16816(acc[mt][2 * nt + 1], al[mt], bh[nt][1], bh[nt][3]);
                    }
                }
        }
        __syncthreads();
    }

    const int lr = lane >> 2;
    const int lc = (lane & 3) << 1;
#pragma unroll
    for (int mt = 0; mt < 2; mt++) {
        const int mBase = m0 + wM * 32 + mt * 16 + lr;
#pragma unroll
        for (int nt = 0; nt < 8; nt++) {
            const int n = n0 + wN * 64 + nt * 8 + lc;
            const float b0 = bias[n], b1 = bias[n + 1];
            float2 v0 = make_float2(acc[mt][nt][0] + b0, acc[mt][nt][1] + b1);
            float2 v1 = make_float2(acc[mt][nt][2] + b0, acc[mt][nt][3] + b1);
            size_t o0, o1;
            if (MODE == 3) {
                o0 = (size_t)mBase * (Tn * Cn) + (size_t)ldc_or_slot * Cn + n;
                o1 = (size_t)(mBase + 8) * (Tn * Cn) + (size_t)ldc_or_slot * Cn + n;
            } else {
                o0 = (size_t)mBase * ldc_or_slot + n;
                o1 = (size_t)(mBase + 8) * ldc_or_slot + n;
            }
            if (OUTH) {
                __half* C = (__half*)Cv;
                *(__half2*)(C + o0) = __floats2half2_rn(v0.x, v0.y);
                *(__half2*)(C + o1) = __floats2half2_rn(v1.x, v1.y);
            } else {
                float* C = (float*)Cv;
                *(float2*)(C + o0) = v0;
                *(float2*)(C + o1) = v1;
            }
        }
    }
}

// ---------------------------------------------------------------------------
// Layer-0 GRU step (t>=1), fp16 carried state. GH GEMM + gate math.
// GIMODE: 1 = fp32 bias row; 2 = fp16 token table.
// ---------------------------------------------------------------------------
template <int GIMODE>
__global__ void __launch_bounds__(256, 2)
gru_step(const __half* __restrict__ Ahi,
         const __half* __restrict__ W, const float* __restrict__ bhh,
         const void* __restrict__ GIt, const int* __restrict__ gt, int step,
         float* __restrict__ houtF, __half* __restrict__ hi)
{
    extern __shared__ __align__(128) char smem[];
    const uint32_t sb = smem_u32(smem);
    const int tid  = threadIdx.x;
    const int wid  = tid >> 5, lane = tid & 31;
    const int wM   = wid >> 1;
    const int wN   = wid & 1;
    const int m0   = blockIdx.y << 7;
    const int j0   = blockIdx.x << 5;

    const char* gAh = (const char*)(Ahi + (size_t)m0 * KDIM);
    const char* gW  = (const char*)W;

    int srow[4], soff[4]; uint32_t sso[4];
#pragma unroll
    for (int q = 0; q < 4; q++) {
        int id = tid * 4 + q;
        srow[q] = id >> 3;
        soff[q] = (id & 7) << 4;
        sso[q]  = (uint32_t)((srow[q] << 7) | (soff[q] ^ ((srow[q] & 7) << 4)));
    }
    int bgr[3], boff[3]; uint32_t bso[3];
#pragma unroll
    for (int q = 0; q < 3; q++) {
        int id = tid * 3 + q;
        int rb = id >> 3;
        boff[q] = (id & 7) << 4;
        bgr[q]  = j0 + (rb & 31) + (rb >> 5) * 512;
        bso[q]  = (uint32_t)((rb << 7) | (boff[q] ^ ((rb & 7) << 4)));
    }

    const int lr16 = lane & 15;
    const int lhi  = (lane >> 4) << 4;
    uint32_t aBase[2], aXr[2];
#pragma unroll
    for (int mt = 0; mt < 2; mt++) {
        int r = wM * 32 + mt * 16 + lr16;
        aBase[mt] = (uint32_t)(r << 7);
        aXr[mt]   = ((r & 7) << 4);
    }
    uint32_t bBase[3], bXr[3];
#pragma unroll
    for (int g = 0; g < 3; g++) {
        int r = wN * 16 + g * 32 + lr16;
        bBase[g] = (uint32_t)(r << 7);
        bXr[g]   = ((r & 7) << 4);
    }

    float acc[2][3][2][4];
#pragma unroll
    for (int i = 0; i < 2; i++)
#pragma unroll
        for (int g = 0; g < 3; g++)
#pragma unroll
            for (int a = 0; a < 2; a++)
#pragma unroll
                for (int v = 0; v < 4; v++) acc[i][g][a][v] = 0.f;

    auto load_chunk = [&](int s, int c) {
        const uint32_t st = sb + s * 28672;
        const int cb = c * 128;
#pragma unroll
        for (int q = 0; q < 4; q++) {
            int go = srow[q] * 1024 + cb + soff[q];
            cpasync16(st + sso[q], gAh + go);
        }
#pragma unroll
        for (int q = 0; q < 3; q++) {
            int go = bgr[q] * 1024 + cb + boff[q];
            cpasync16(st + 16384 + bso[q], gW + go);
        }
        cp_commit();
    };

    load_chunk(0, 0);
    load_chunk(1, 1);

#pragma unroll
    for (int c = 0; c < NCH; c++) {
        const int s = c % 3;
        if (c + 2 < NCH) { load_chunk((c + 2) % 3, c + 2); cp_wait<2>(); }
        else if (c + 1 < NCH) cp_wait<1>();
        else                  cp_wait<0>();
        __syncthreads();

        const uint32_t stA0 = sb + s * 28672;
        const uint32_t stB0 = stA0 + 16384;

#pragma unroll
        for (int k16 = 0; k16 < 4; k16++) {
            const uint32_t ko = (uint32_t)(k16 * 32 + lhi);
            uint32_t ah[2][4];
#pragma unroll
            for (int mt = 0; mt < 2; mt++)
                ldsm4(ah[mt][0], ah[mt][1], ah[mt][2], ah[mt][3],
                      stA0 + aBase[mt] + (ko ^ aXr[mt]));
            uint32_t bh[3][4];
#pragma unroll
            for (int g = 0; g < 3; g++)
                ldsm4(bh[g][0], bh[g][1], bh[g][2], bh[g][3],
                      stB0 + bBase[g] + (ko ^ bXr[g]));
#pragma unroll
            for (int mt = 0; mt < 2; mt++)
#pragma unroll
                for (int g = 0; g < 3; g++) {
                    hmma16816(acc[mt][g][0], ah[mt], bh[g][0], bh[g][2]);
                    hmma16816(acc[mt][g][1], ah[mt], bh[g][1], bh[g][3]);
                }
        }
        __syncthreads();
    }

    const int lr = lane >> 2;
    const int lc = (lane & 3) << 1;
#pragma unroll
    for (int mt = 0; mt < 2; mt++) {
        const int mBase = m0 + wM * 32 + mt * 16 + lr;
#pragma unroll
        for (int a = 0; a < 2; a++) {
            const int j = j0 + wN * 16 + a * 8 + lc;
            const float2 bR = *(const float2*)(bhh + j);
            const float2 bZ = *(const float2*)(bhh + 512 + j);
            const float2 bN = *(const float2*)(bhh + 1024 + j);
#pragma unroll
            for (int hh = 0; hh < 2; hh++) {
                const int row = mBase + hh * 8;
                const int vi = hh * 2;
                float2 gR, gZ, gN;
                if (GIMODE == 1) {
                    const float* gi = (const float*)GIt + j;
                    gR = *(const float2*)(gi);
                    gZ = *(const float2*)(gi + 512);
                    gN = *(const float2*)(gi + 1024);
                } else {
                    int tok = gt[row * Tn + (step - 2)];
                    const __half* gi = (const __half*)GIt + (size_t)tok * H3 + j;
                    gR = __half22float2(*(const __half2*)(gi));
                    gZ = __half22float2(*(const __half2*)(gi + 512));
                    gN = __half22float2(*(const __half2*)(gi + 1024));
                }
                float2 hp = __half22float2(
                    *(const __half2*)(Ahi + (size_t)row * Hn + j));
                float r0 = sigf(gR.x + acc[mt][0][a][vi]     + bR.x);
                float r1 = sigf(gR.y + acc[mt][0][a][vi + 1] + bR.y);
                float z0 = sigf(gZ.x + acc[mt][1][a][vi]     + bZ.x);
                float z1 = sigf(gZ.y + acc[mt][1][a][vi + 1] + bZ.y);
                float n0 = tanhf(gN.x + r0 * (acc[mt][2][a][vi]     + bN.x));
                float n1 = tanhf(gN.y + r1 * (acc[mt][2][a][vi + 1] + bN.y));
                float h0 = (1.f - z0) * n0 + z0 * hp.x;
                float h1 = (1.f - z1) * n1 + z1 * hp.y;
                size_t oh = (size_t)row * Hn + j;
                if (houtF) *(float2*)(houtF + oh) = make_float2(h0, h1);
                *(__half2*)(hi + oh) = __floats2half2_rn(h0, h1);
            }
        }
    }
}

// ---------------------------------------------------------------------------
// MERGED step: K-concatenated GH+GI, fp16 carried state. Used for layers 1/2
// every step, and layer 0 at t=0 (Ax = x0).
// Chunks 0-7: A = h_{t-1}, B = Whh. Chunks 8-15: A = x, B = Wih.
// ---------------------------------------------------------------------------
__global__ void __launch_bounds__(256, 2)
gru_step2(const __half* __restrict__ Ah, const __half* __restrict__ Ax,
          const __half* __restrict__ Whh, const __half* __restrict__ Wih,
          const float* __restrict__ bhh, const float* __restrict__ bih,
          float* __restrict__ houtF, __half* __restrict__ hi)
{
    extern __shared__ __align__(128) char smem[];
    const uint32_t sb = smem_u32(smem);
    const int tid  = threadIdx.x;
    const int wid  = tid >> 5, lane = tid & 31;
    const int wM   = wid >> 1;
    const int wN   = wid & 1;
    const int m0   = blockIdx.y << 7;
    const int j0   = blockIdx.x << 5;

    const char* gAh = (const char*)(Ah + (size_t)m0 * KDIM);
    const char* gAx = (const char*)(Ax + (size_t)m0 * KDIM);
    const char* gWh = (const char*)Whh;
    const char* gWi = (const char*)Wih;

    int srow[4], soff[4]; uint32_t sso[4];
#pragma unroll
    for (int q = 0; q < 4; q++) {
        int id = tid * 4 + q;
        srow[q] = id >> 3;
        soff[q] = (id & 7) << 4;
        sso[q]  = (uint32_t)((srow[q] << 7) | (soff[q] ^ ((srow[q] & 7) << 4)));
    }
    int bgr[3], boff[3]; uint32_t bso[3];
#pragma unroll
    for (int q = 0; q < 3; q++) {
        int id = tid * 3 + q;
        int rb = id >> 3;
        boff[q] = (id & 7) << 4;
        bgr[q]  = j0 + (rb & 31) + (rb >> 5) * 512;
        bso[q]  = (uint32_t)((rb << 7) | (boff[q] ^ ((rb & 7) << 4)));
    }

    const int lr16 = lane & 15;
    const int lhi  = (lane >> 4) << 4;
    uint32_t aBase[2], aXr[2];
#pragma unroll
    for (int mt = 0; mt < 2; mt++) {
        int r = wM * 32 + mt * 16 + lr16;
        aBase[mt] = (uint32_t)(r << 7);
        aXr[mt]   = ((r & 7) << 4);
    }
    uint32_t bBase[3], bXr[3];
#pragma unroll
    for (int g = 0; g < 3; g++) {
        int r = wN * 16 + g * 32 + lr16;
        bBase[g] = (uint32_t)(r << 7);
        bXr[g]   = ((r & 7) << 4);
    }

    // acc groups: 0=r (combined), 1=z (combined), 2=n_h, 3=n_i
    float acc[2][4][2][4];
#pragma unroll
    for (int i = 0; i < 2; i++)
#pragma unroll
        for (int g = 0; g < 4; g++)
#pragma unroll
            for (int a = 0; a < 2; a++)
#pragma unroll
                for (int v = 0; v < 4; v++) acc[i][g][a][v] = 0.f;

    auto load_chunk = [&](int s, int c) {
        const uint32_t st = sb + s * 28672;
        const char* gA = (c < NCH) ? gAh : gAx;
        const char* gW = (c < NCH) ? gWh : gWi;
        const int cb = (c & 7) * 128;
#pragma unroll
        for (int q = 0; q < 4; q++) {
            int go = srow[q] * 1024 + cb + soff[q];
            cpasync16(st + sso[q], gA + go);
        }
#pragma unroll
        for (int q = 0; q < 3; q++) {
            int go = bgr[q] * 1024 + cb + boff[q];
            cpasync16(st + 16384 + bso[q], gW + go);
        }
        cp_commit();
    };

    load_chunk(0, 0);
    load_chunk(1, 1);

#pragma unroll
    for (int c = 0; c < 2 * NCH; c++) {
        const int s = c % 3;
        if (c + 2 < 2 * NCH) { load_chunk((c + 2) % 3, c + 2); cp_wait<2>(); }
        else if (c + 1 < 2 * NCH) cp_wait<1>();
        else                      cp_wait<0>();
        __syncthreads();

        const uint32_t stA0 = sb + s * 28672;
        const uint32_t stB0 = stA0 + 16384;
        const int ng = (c < NCH) ? 2 : 3;

#pragma unroll
        for (int k16 = 0; k16 < 4; k16++) {
            const uint32_t ko = (uint32_t)(k16 * 32 + lhi);
            uint32_t ah[2][4];
#pragma unroll
            for (int mt = 0; mt < 2; mt++)
                ldsm4(ah[mt][0], ah[mt][1], ah[mt][2], ah[mt][3],
                      stA0 + aBase[mt] + (ko ^ aXr[mt]));
            uint32_t bh[3][4];
#pragma unroll
            for (int g = 0; g < 3; g++)
                ldsm4(bh[g][0], bh[g][1], bh[g][2], bh[g][3],
                      stB0 + bBase[g] + (ko ^ bXr[g]));
#pragma unroll
            for (int mt = 0; mt < 2; mt++) {
                hmma16816(acc[mt][0][0], ah[mt], bh[0][0], bh[0][2]);
                hmma16816(acc[mt][0][1], ah[mt], bh[0][1], bh[0][3]);
                hmma16816(acc[mt][1][0], ah[mt], bh[1][0], bh[1][2]);
                hmma16816(acc[mt][1][1], ah[mt], bh[1][1], bh[1][3]);
                hmma16816(acc[mt][ng][0], ah[mt], bh[2][0], bh[2][2]);
                hmma16816(acc[mt][ng][1], ah[mt], bh[2][1], bh[2][3]);
            }
        }
        __syncthreads();
    }

    const int lr = lane >> 2;
    const int lc = (lane & 3) << 1;
#pragma unroll
    for (int mt = 0; mt < 2; mt++) {
        const int mBase = m0 + wM * 32 + mt * 16 + lr;
#pragma unroll
        for (int a = 0; a < 2; a++) {
            const int j = j0 + wN * 16 + a * 8 + lc;
            const float2 bhR = *(const float2*)(bhh + j);
            const float2 bhZ = *(const float2*)(bhh + 512 + j);
            const float2 bhN = *(const float2*)(bhh + 1024 + j);
            const float2 biR = *(const float2*)(bih + j);
            const float2 biZ = *(const float2*)(bih + 512 + j);
            const float2 biN = *(const float2*)(bih + 1024 + j);
#pragma unroll
            for (int hh = 0; hh < 2; hh++) {
                const int row = mBase + hh * 8;
                const int vi = hh * 2;
                float2 hp = __half22float2(
                    *(const __half2*)(Ah + (size_t)row * Hn + j));
                float r0 = sigf(acc[mt][0][a][vi]     + bhR.x + biR.x);
                float r1 = sigf(acc[mt][0][a][vi + 1] + bhR.y + biR.y);
                float z0 = sigf(acc[mt][1][a][vi]     + bhZ.x + biZ.x);
                float z1 = sigf(acc[mt][1][a][vi + 1] + bhZ.y + biZ.y);
                float n0 = tanhf(acc[mt][3][a][vi]     + biN.x
                                 + r0 * (acc[mt][2][a][vi]     + bhN.x));
                float n1 = tanhf(acc[mt][3][a][vi + 1] + biN.y
                                 + r1 * (acc[mt][2][a][vi + 1] + bhN.y));
                float h0 = (1.f - z0) * n0 + z0 * hp.x;
                float h1 = (1.f - z1) * n1 + z1 * hp.y;
                size_t oh = (size_t)row * Hn + j;
                if (houtF) *(float2*)(houtF + oh) = make_float2(h0, h1);
                *(__half2*)(hi + oh) = __floats2half2_rn(h0, h1);
            }
        }
    }
}

// ---------------- elementwise kernels ----------------
__global__ void convW(const float* __restrict__ W_ih, const float* __restrict__ W_hh,
                      const float* __restrict__ W_out, const float* __restrict__ W_tp,
                      const float* __restrict__ emb,
                      __half* __restrict__ wih, __half* __restrict__ whh,
                      __half* __restrict__ wo,  __half* __restrict__ wt,
                      __half* __restrict__ embh, __half* __restrict__ embl)
{
    int i = blockIdx.x * blockDim.x + threadIdx.x;
    if (i >= 1376256) return;
    if (i < 1310720) {
        const float* s; __half* d; int j;
        if (i < 589824)       { s = W_ih;  d = wih; j = i; }
        else if (i < 1179648) { s = W_hh;  d = whh; j = i - 589824; }
        else if (i < 1245184) { s = W_out; d = wo;  j = i - 1179648; }
        else                  { s = W_tp;  d = wt;  j = i - 1245184; }
        float4 v = ((const float4*)s)[j];
        ((__half2*)d)[2 * j + 0] = __floats2half2_rn(v.x, v.y);
        ((__half2*)d)[2 * j + 1] = __floats2half2_rn(v.z, v.w);
    } else {
        int j = i - 1310720;
        float4 v = ((const float4*)emb)[j];
        __half h0, h1, h2, h3, l0, l1, l2, l3;
        split1h(v.x, h0, l0); split1h(v.y, h1, l1);
        split1h(v.z, h2, l2); split1h(v.w, h3, l3);
        ((__half2*)embh)[2 * j + 0] = __halves2half2(h0, h1);
        ((__half2*)embh)[2 * j + 1] = __halves2half2(h2, h3);
        ((__half2*)embl)[2 * j + 0] = __halves2half2(l0, l1);
        ((__half2*)embl)[2 * j + 1] = __halves2half2(l2, l3);
    }
}

// prev hidden -> fp16; x0 compute -> fp16 (single plane)
__global__ void prep_kernel(const float* __restrict__ prev,
                            const float* __restrict__ action,
                            const float* __restrict__ W_a, const float* __restrict__ b_a,
                            __half* __restrict__ pqh, __half* __restrict__ x0h)
{
    const int NPREV = (int)(Ln * BH / 4);
    int i = blockIdx.x * blockDim.x + threadIdx.x;
    if (i < NPREV) {
        float4 v = ((const float4*)prev)[i];
        ((__half2*)pqh)[2 * i + 0] = __floats2half2_rn(v.x, v.y);
        ((__half2*)pqh)[2 * i + 1] = __floats2half2_rn(v.z, v.w);
    } else if (i < NPREV + (int)(BH / 4)) {
        int j = i - NPREV;
        int e0 = j * 4;
        int b = e0 >> 9, c = e0 & 511;
        float a0 = action[b * 3 + 0], a1 = action[b * 3 + 1], a2 = action[b * 3 + 2];
        float s0 = b_a[c + 0] + a0 * W_a[(c + 0) * 3 + 0] + a1 * W_a[(c + 0) * 3 + 1]
                              + a2 * W_a[(c + 0) * 3 + 2];
        float s1 = b_a[c + 1] + a0 * W_a[(c + 1) * 3 + 0] + a1 * W_a[(c + 1) * 3 + 1]
                              + a2 * W_a[(c + 1) * 3 + 2];
        float s2 = b_a[c + 2] + a0 * W_a[(c + 2) * 3 + 0] + a1 * W_a[(c + 2) * 3 + 1]
                              + a2 * W_a[(c + 2) * 3 + 2];
        float s3 = b_a[c + 3] + a0 * W_a[(c + 3) * 3 + 0] + a1 * W_a[(c + 3) * 3 + 1]
                              + a2 * W_a[(c + 3) * 3 + 2];
        ((__half2*)x0h)[2 * j + 0] = __floats2half2_rn(s0, s1);
        ((__half2*)x0h)[2 * j + 1] = __floats2half2_rn(s2, s3);
    }
}

__global__ void split2_kernel(const float* __restrict__ src,
                              __half* __restrict__ hi, __half* __restrict__ lo, int n4)
{
    int i = blockIdx.x * blockDim.x + threadIdx.x;
    if (i >= n4) return;
    float4 v = ((const float4*)src)[i];
    __half h0, h1, h2, h3, l0, l1, l2, l3;
    split1h(v.x, h0, l0); split1h(v.y, h1, l1);
    split1h(v.z, h2, l2); split1h(v.w, h3, l3);
    ((__half2*)hi)[2 * i + 0] = __halves2half2(h0, h1);
    ((__half2*)hi)[2 * i + 1] = __halves2half2(h2, h3);
    ((__half2*)lo)[2 * i + 0] = __halves2half2(l0, l1);
    ((__half2*)lo)[2 * i + 1] = __halves2half2(l2, l3);
}

// heads from fp16 h2 (layer-2 output at slot 0)
__global__ void heads_kernel(const __half* __restrict__ h2, const float* __restrict__ W_r,
                             const float* __restrict__ b_r, const float* __restrict__ W_d,
                             const float* __restrict__ b_d,
                             float* __restrict__ outr, float* __restrict__ outd)
{
    int gw = (blockIdx.x * blockDim.x + threadIdx.x) >> 5;
    int lane = threadIdx.x & 31;
    if (gw >= Bsz) return;
    const __half* hb = h2 + (size_t)gw * Hn;
    float sr = 0.f, sd = 0.f;
#pragma unroll
    for (int k = lane; k < Hn; k += 32) {
        float v = __half2float(hb[k]);
        sr = fmaf(v, W_r[k], sr);
        sd = fmaf(v, W_d[k], sd);
    }
#pragma unroll
    for (int o = 16; o > 0; o >>= 1) {
        sr += __shfl_down_sync(0xffffffffu, sr, o);
        sd += __shfl_down_sync(0xffffffffu, sd, o);
    }
    if (lane == 0) { outr[gw] = sr + b_r[0]; outd[gw] = sd + b_d[0]; }
}

// ---------------------------------------------------------------------------
extern "C" void kernel_launch(void* const* d_in, const int* in_sizes, int n_in,
                              void* d_out, int out_size)
{
    const float* action      = (const float*)d_in[0];
    const float* prev_hidden = (const float*)d_in[1];
    const int*   gt          = (const int*)d_in[2];
    const float* W_a         = (const float*)d_in[3];
    const float* b_a         = (const float*)d_in[4];
    const float* emb         = (const float*)d_in[5];
    const float* W_tp        = (const float*)d_in[6];
    const float* b_tp        = (const float*)d_in[7];
    const float* W_ih        = (const float*)d_in[8];
    const float* W_hh        = (const float*)d_in[9];
    const float* b_ih        = (const float*)d_in[10];
    const float* b_hh        = (const float*)d_in[11];
    const float* W_out       = (const float*)d_in[12];
    const float* b_out       = (const float*)d_in[13];
    const float* W_r         = (const float*)d_in[14];
    const float* b_r         = (const float*)d_in[15];
    const float* W_d         = (const float*)d_in[16];
    const float* b_d         = (const float*)d_in[17];
    float* out = (float*)d_out;

    static cudaStream_t sL1 = nullptr, sL2 = nullptr, sLg = nullptr;
    static cudaEvent_t evL0[NSTEP], evL1[NSTEP], evL2[NSTEP], evLg[NSTEP];
    static cudaEvent_t evPre, evGtab;
    if (!sL1) {
        cudaStreamCreateWithFlags(&sL1, cudaStreamNonBlocking);
        cudaStreamCreateWithFlags(&sL2, cudaStreamNonBlocking);
        cudaStreamCreateWithFlags(&sLg, cudaStreamNonBlocking);
        for (int i = 0; i < NSTEP; i++) {
            cudaEventCreateWithFlags(&evL0[i], cudaEventDisableTiming);
            cudaEventCreateWithFlags(&evL1[i], cudaEventDisableTiming);
            cudaEventCreateWithFlags(&evL2[i], cudaEventDisableTiming);
            cudaEventCreateWithFlags(&evLg[i], cudaEventDisableTiming);
        }
        cudaEventCreateWithFlags(&evPre, cudaEventDisableTiming);
        cudaEventCreateWithFlags(&evGtab, cudaEventDisableTiming);
        cudaFuncSetAttribute((const void*)gemm_h2<0, 2, 0>, cudaFuncAttributeMaxDynamicSharedMemorySize, GEMM_SMEM2);
        cudaFuncSetAttribute((const void*)gemm_h2<0, 2, 1>, cudaFuncAttributeMaxDynamicSharedMemorySize, GEMM_SMEM2);
        cudaFuncSetAttribute((const void*)gemm_h2<3, 1, 0>, cudaFuncAttributeMaxDynamicSharedMemorySize, GEMM_SMEM1);
        cudaFuncSetAttribute((const void*)gru_step<1>, cudaFuncAttributeMaxDynamicSharedMemorySize, STEP_SMEM);
        cudaFuncSetAttribute((const void*)gru_step<2>, cudaFuncAttributeMaxDynamicSharedMemorySize, STEP_SMEM);
        cudaFuncSetAttribute((const void*)gru_step2, cudaFuncAttributeMaxDynamicSharedMemorySize, STEP_SMEM);
    }

    __half *u0, *u1, *u2, *x0h, *pqh;
    __half *wih, *whh, *wo, *wt, *embh, *embl, *Pqh, *Pql, *Gtabh;
    float *P;
    cudaGetSymbolAddress((void**)&u0, g_u0);
    cudaGetSymbolAddress((void**)&u1, g_u1);
    cudaGetSymbolAddress((void**)&u2, g_u2);
    cudaGetSymbolAddress((void**)&x0h, g_x0h);
    cudaGetSymbolAddress((void**)&pqh, g_pq_hi);
    cudaGetSymbolAddress((void**)&wih, g_wih);   cudaGetSymbolAddress((void**)&whh, g_whh);
    cudaGetSymbolAddress((void**)&wo,  g_wo);    cudaGetSymbolAddress((void**)&wt,  g_wt);
    cudaGetSymbolAddress((void**)&embh, g_embh); cudaGetSymbolAddress((void**)&embl, g_embl);
    cudaGetSymbolAddress((void**)&Pqh, g_Pqh);   cudaGetSymbolAddress((void**)&Pql, g_Pql);
    cudaGetSymbolAddress((void**)&P, g_P);
    cudaGetSymbolAddress((void**)&Gtabh, g_Gtabh);

    float* outLogits = out;
    float* outReward = out + (size_t)Bsz * Tn * Cn;
    float* outDone   = outReward + Bsz;
    float* outFinal  = outDone + Bsz;

    const dim3 stepGrid(16, 32);

    // ---- preamble (main stream) ----
    convW<<<(1376256 + 255) / 256, 256>>>(W_ih, W_hh, W_out, W_tp, emb,
                                          wih, whh, wo, wt, embh, embl);
    prep_kernel<<<((int)(Ln * BH / 4 + BH / 4) + 255) / 256, 256>>>(
        prev_hidden, action, W_a, b_a, pqh, x0h);
    cudaEventRecord(evPre, 0);

    // P / Gtab chain on side stream (overlaps L0 t=0..1)
    cudaStreamWaitEvent(sLg, evPre, 0);
    gemm_h2<0, 2, 0><<<dim3(4, 4), 256, GEMM_SMEM2, sLg>>>(embh, embl, wt, b_tp, P, Hn);
    split2_kernel<<<((Cn * Hn / 4) + 255) / 256, 256, 0, sLg>>>(P, Pqh, Pql, Cn * Hn / 4);
    gemm_h2<0, 2, 1><<<dim3(12, 4), 256, GEMM_SMEM2, sLg>>>(Pqh, Pql, wih, b_ih, Gtabh, H3);
    cudaEventRecord(evGtab, sLg);

    // ---- layer 0 recurrence on main stream (fp16 carried state) ----
    // t=0: merged step with x = x0 (computes GI and GH together)
    gru_step2<<<stepGrid, 256, STEP_SMEM>>>(
        pqh, x0h, whh, wih, b_hh, b_ih, nullptr, u0);
    cudaEventRecord(evL0[0], 0);
    for (int t = 1; t < NSTEP; t++) {
        if (t == 2) cudaStreamWaitEvent(0, evGtab, 0);
        const __half* ph = u0 + (size_t)(t - 1) * BH;
        float* hF = (t == 16) ? outFinal : nullptr;
        __half* oh = u0 + (size_t)t * BH;
        if (t == 1)
            gru_step<1><<<stepGrid, 256, STEP_SMEM>>>(ph, whh, b_hh,
                                                      b_ih, gt, t, hF, oh);
        else
            gru_step<2><<<stepGrid, 256, STEP_SMEM>>>(ph, whh, b_hh,
                                                      Gtabh, gt, t, hF, oh);
        cudaEventRecord(evL0[t], 0);
    }

    // ---- layer 1 recurrence on sL1 (merged GI+GH steps) ----
    for (int t = 0; t < NSTEP; t++) {
        cudaStreamWaitEvent(sL1, evL0[t], 0);
        const __half* ph = t ? (u1 + (size_t)(t - 1) * BH) : (pqh + BH);
        float* hF = (t == 16) ? (outFinal + BH) : nullptr;
        gru_step2<<<stepGrid, 256, STEP_SMEM, sL1>>>(
            ph, u0 + (size_t)t * BH,
            whh + (size_t)1 * H3 * Hn, wih + (size_t)1 * H3 * Hn,
            b_hh + 1 * H3, b_ih + 1 * H3,
            hF, u1 + (size_t)t * BH);
        cudaEventRecord(evL1[t], sL1);
    }

    // ---- layer 2 recurrence on sL2 (merged GI+GH steps) ----
    for (int t = 0; t < NSTEP; t++) {
        cudaStreamWaitEvent(sL2, evL1[t], 0);
        const __half* ph = t ? (u2 + (size_t)(t - 1) * BH) : (pqh + 2 * BH);
        float* hF = (t == 16) ? (outFinal + 2 * BH) : nullptr;
        gru_step2<<<stepGrid, 256, STEP_SMEM, sL2>>>(
            ph, u1 + (size_t)t * BH,
            whh + (size_t)2 * H3 * Hn, wih + (size_t)2 * H3 * Hn,
            b_hh + 2 * H3, b_ih + 2 * H3,
            hF, u2 + (size_t)t * BH);
        cudaEventRecord(evL2[t], sL2);
    }

    // ---- logits chunks on sLg (slot t -> logits position t-1) ----
    for (int t = 1; t < NSTEP; t++) {
        cudaStreamWaitEvent(sLg, evL2[t], 0);
        gemm_h2<3, 1, 0><<<dim3(4, 32), 256, GEMM_SMEM1, sLg>>>(
            u2 + (size_t)t * BH, nullptr, wo, b_out, outLogits, t - 1);
        cudaEventRecord(evLg[t], sLg);
    }

    // ---- epilogue on main stream ----
    cudaStreamWaitEvent(0, evL2[0], 0);
    heads_kernel<<<(Bsz * 32 + 255) / 256, 256>>>(
        u2, W_r, b_r, W_d, b_d, outReward, outDone);
    cudaStreamWaitEvent(0, evL1[16], 0);
    cudaStreamWaitEvent(0, evL2[16], 0);
    for (int t = 1; t < NSTEP; t++)
        cudaStreamWaitEvent(0, evLg[t], 0);
}